// round 14
// baseline (speedup 1.0000x reference)
#include <cuda_runtime.h>
#include <cuda_bf16.h>
#include <cstdint>

#define TSEQ 2048
#define EDIM 1024
#define HD   32
#define DV   64
#define NQH  32
#define NH   16
#define LAMBDA_INIT_C 0.47071301834358415f

// ---------------- scratch ----------------
__device__ float g_lambda;
__device__ __nv_bfloat16 g_xh[TSEQ * EDIM],  g_xl[TSEQ * EDIM];
__device__ __nv_bfloat16 g_wqh[EDIM * EDIM], g_wql[EDIM * EDIM];
__device__ __nv_bfloat16 g_wkh[EDIM * EDIM], g_wkl[EDIM * EDIM];
__device__ __nv_bfloat16 g_wvh[EDIM * EDIM], g_wvl[EDIM * EDIM];
__device__ __nv_bfloat16 g_woh[EDIM * EDIM], g_wol[EDIM * EDIM];
__device__ __nv_bfloat16 g_ah[TSEQ * EDIM],  g_al[TSEQ * EDIM];
__device__ __nv_bfloat16 g_qh[TSEQ * EDIM],  g_ql[TSEQ * EDIM];
__device__ __nv_bfloat16 g_kh[TSEQ * EDIM],  g_kl[TSEQ * EDIM];
__device__ __nv_bfloat16 g_vh[TSEQ * EDIM],  g_vl[TSEQ * EDIM];

// ---------------- helpers ----------------
__device__ __forceinline__ uint32_t smem_u32(const void* p) {
    uint32_t a;
    asm("{ .reg .u64 t; cvta.to.shared.u64 t, %1; cvt.u32.u64 %0, t; }" : "=r"(a) : "l"(p));
    return a;
}
__device__ __forceinline__ void ldm_x4(uint32_t* r, uint32_t addr) {
    asm volatile("ldmatrix.sync.aligned.m8n8.x4.shared.b16 {%0,%1,%2,%3}, [%4];"
                 : "=r"(r[0]), "=r"(r[1]), "=r"(r[2]), "=r"(r[3]) : "r"(addr));
}
__device__ __forceinline__ void ldm_x4_t(uint32_t* r, uint32_t addr) {
    asm volatile("ldmatrix.sync.aligned.m8n8.x4.trans.shared.b16 {%0,%1,%2,%3}, [%4];"
                 : "=r"(r[0]), "=r"(r[1]), "=r"(r[2]), "=r"(r[3]) : "r"(addr));
}
__device__ __forceinline__ void hmma(float* d, const uint32_t* a, const uint32_t* b) {
    asm volatile("mma.sync.aligned.m16n8k16.row.col.f32.bf16.bf16.f32 "
                 "{%0,%1,%2,%3}, {%4,%5,%6,%7}, {%8,%9}, {%0,%1,%2,%3};"
                 : "+f"(d[0]), "+f"(d[1]), "+f"(d[2]), "+f"(d[3])
                 : "r"(a[0]), "r"(a[1]), "r"(a[2]), "r"(a[3]), "r"(b[0]), "r"(b[1]));
}
#define CP_ASYNC16(s, g) asm volatile("cp.async.cg.shared.global [%0], [%1], 16;" :: "r"(s), "l"(g))
#define CP_COMMIT()      asm volatile("cp.async.commit_group;" ::: "memory")
#define CP_WAIT1()       asm volatile("cp.async.wait_group 1;" ::: "memory")
#define CP_WAIT2()       asm volatile("cp.async.wait_group 2;" ::: "memory")

// 2^(x*SCL2E), SCL2E = (1/sqrt(32))*log2(e)
__device__ __forceinline__ float fexps(float x) {
    const float SCL2E = 0.25506943387767815f;
    float y = fmaf(x, SCL2E, 12582912.0f);
    int   n = __float_as_int(y) - 0x4B400000;
    float r = fmaf(x, SCL2E, -(y - 12582912.0f));
    float t = 0.00133335581f;
    t = fmaf(t, r, 0.00961812910f);
    t = fmaf(t, r, 0.05550410866f);
    t = fmaf(t, r, 0.24022650695f);
    t = fmaf(t, r, 0.69314718056f);
    t = fmaf(t, r, 1.0f);
    return __int_as_float(__float_as_int(t) + (n << 23));
}
__device__ __forceinline__ uint32_t packsplit(float a, float b, uint32_t& lo) {
    __nv_bfloat16 ha = __float2bfloat16(a), hb = __float2bfloat16(b);
    __nv_bfloat162 l2 = __halves2bfloat162(
        __float2bfloat16(a - __bfloat162float(ha)),
        __float2bfloat16(b - __bfloat162float(hb)));
    lo = *(uint32_t*)&l2;
    __nv_bfloat162 h2 = __halves2bfloat162(ha, hb);
    return *(uint32_t*)&h2;
}
__device__ __forceinline__ void store_split2(__nv_bfloat16* H, __nv_bfloat16* L,
                                             size_t i, float a, float b) {
    __nv_bfloat16 ha = __float2bfloat16(a), hb = __float2bfloat16(b);
    *(__nv_bfloat162*)(H + i) = __halves2bfloat162(ha, hb);
    *(__nv_bfloat162*)(L + i) = __halves2bfloat162(
        __float2bfloat16(a - __bfloat162float(ha)),
        __float2bfloat16(b - __bfloat162float(hb)));
}

// ---------------- fp32 -> (hi, lo) bf16 split ----------------
__global__ __launch_bounds__(256)
void split_kernel(const float* __restrict__ x, __nv_bfloat16* __restrict__ hi,
                  __nv_bfloat16* __restrict__ lo)
{
    int i = (blockIdx.x * 256 + threadIdx.x) * 4;
    float4 v = *(const float4*)(x + i);
    store_split2(hi, lo, i,     v.x, v.y);
    store_split2(hi, lo, i + 2, v.z, v.w);
}

// ============================================================================
// HMMA bf16x3 GEMM body (NT), 128x128 tile, BK=32, 3-stage cp.async.
// ============================================================================
#define GSTR   80
#define GTILEB (128 * GSTR)
#define GSTAGE (4 * GTILEB)
#define GSMEM  (3 * GSTAGE)

template<bool BF16OUT>
__device__ __forceinline__
void gemm_body(const __nv_bfloat16* __restrict__ Ah, const __nv_bfloat16* __restrict__ Al,
               const __nv_bfloat16* __restrict__ Bh, const __nv_bfloat16* __restrict__ Bl,
               float* __restrict__ C, __nv_bfloat16* __restrict__ Ch,
               __nv_bfloat16* __restrict__ Cl, int bm, int bn, char* sm)
{
    const uint32_t sb = smem_u32(sm);
    const int tid  = threadIdx.x;
    const int lane = tid & 31;
    const int wid  = tid >> 5;
    const int wm   = wid >> 2;
    const int wn   = wid & 3;

    const int lt = tid >> 6;
    const int u  = tid & 63;
    const int lrow0 = u >> 2;
    const int lcseg = (u & 3) * 16;
    const char* gsrc;
    {
        const char* s0 = (const char*)(Ah + (size_t)bm * EDIM);
        const char* s1 = (const char*)(Al + (size_t)bm * EDIM);
        const char* s2 = (const char*)(Bh + (size_t)bn * EDIM);
        const char* s3 = (const char*)(Bl + (size_t)bn * EDIM);
        gsrc = (lt == 0) ? s0 : (lt == 1) ? s1 : (lt == 2) ? s2 : s3;
    }
    const uint32_t sdst0 = sb + lt * GTILEB + lrow0 * GSTR + lcseg;

    auto issue = [&](int c, int st) {
        const char* g = gsrc + (size_t)lrow0 * 2048 + (size_t)c * 64 + lcseg;
        uint32_t s = sdst0 + st * GSTAGE;
#pragma unroll
        for (int i = 0; i < 8; ++i)
            CP_ASYNC16(s + i * 16 * GSTR, g + (size_t)i * 16 * 2048);
        CP_COMMIT();
    };

    const uint32_t offA = (uint32_t)((wm * 64 + (lane & 15)) * GSTR + (lane >> 4) * 16);
    const uint32_t offB = (uint32_t)((wn * 32 + (lane & 7) + (lane >> 4) * 8) * GSTR
                                     + ((lane >> 3) & 1) * 16);

    float acc[4][4][4];
#pragma unroll
    for (int i = 0; i < 4; ++i)
#pragma unroll
        for (int j = 0; j < 4; ++j)
#pragma unroll
            for (int k = 0; k < 4; ++k) acc[i][j][k] = 0.f;

    issue(0, 0);
    issue(1, 1);

    for (int c = 0; c < 32; ++c) {
        CP_WAIT1();
        __syncthreads();
        if (c + 2 < 32) issue(c + 2, (c + 2) % 3);

        const uint32_t stb = sb + (c % 3) * GSTAGE;
        const uint32_t tAh = stb, tAl = stb + GTILEB;
        const uint32_t tBh = stb + 2 * GTILEB, tBl = stb + 3 * GTILEB;

#pragma unroll
        for (int ks = 0; ks < 2; ++ks) {
            const uint32_t ko = ks * 32;
            uint32_t ah[4][4], al[4][4], bh[2][4], bl[2][4];
#pragma unroll
            for (int mf = 0; mf < 4; ++mf) {
                ldm_x4(ah[mf], tAh + offA + mf * (16 * GSTR) + ko);
                ldm_x4(al[mf], tAl + offA + mf * (16 * GSTR) + ko);
            }
#pragma unroll
            for (int nf = 0; nf < 2; ++nf) {
                ldm_x4(bh[nf], tBh + offB + nf * (16 * GSTR) + ko);
                ldm_x4(bl[nf], tBl + offB + nf * (16 * GSTR) + ko);
            }
#pragma unroll
            for (int mf = 0; mf < 4; ++mf)
#pragma unroll
                for (int nf = 0; nf < 4; ++nf) {
                    const uint32_t* BH = &bh[nf >> 1][(nf & 1) * 2];
                    const uint32_t* BL = &bl[nf >> 1][(nf & 1) * 2];
                    hmma(acc[mf][nf], ah[mf], BH);
                    hmma(acc[mf][nf], ah[mf], BL);
                    hmma(acc[mf][nf], al[mf], BH);
                }
        }
        __syncthreads();
    }

    const int mrow = bm + wm * 64 + (lane >> 2);
    const int ncol = bn + wn * 32 + (lane & 3) * 2;
#pragma unroll
    for (int mf = 0; mf < 4; ++mf)
#pragma unroll
        for (int nf = 0; nf < 4; ++nf) {
            size_t i0 = (size_t)(mrow + mf * 16) * EDIM + ncol + nf * 8;
            size_t i1 = i0 + 8 * EDIM;
            if (BF16OUT) {
                store_split2(Ch, Cl, i0, acc[mf][nf][0], acc[mf][nf][1]);
                store_split2(Ch, Cl, i1, acc[mf][nf][2], acc[mf][nf][3]);
            } else {
                *(float2*)(C + i0) = make_float2(acc[mf][nf][0], acc[mf][nf][1]);
                *(float2*)(C + i1) = make_float2(acc[mf][nf][2], acc[mf][nf][3]);
            }
        }
}

// Q/K/V projections in ONE launch: blockIdx.z selects weight & destination.
__global__ __launch_bounds__(256)
void gemm_qkv(const __nv_bfloat16* __restrict__ xh, const __nv_bfloat16* __restrict__ xl,
              const __nv_bfloat16* __restrict__ wqh, const __nv_bfloat16* __restrict__ wql,
              const __nv_bfloat16* __restrict__ wkh, const __nv_bfloat16* __restrict__ wkl,
              const __nv_bfloat16* __restrict__ wvh, const __nv_bfloat16* __restrict__ wvl,
              __nv_bfloat16* __restrict__ qh, __nv_bfloat16* __restrict__ ql,
              __nv_bfloat16* __restrict__ kh, __nv_bfloat16* __restrict__ kl,
              __nv_bfloat16* __restrict__ vh, __nv_bfloat16* __restrict__ vl)
{
    extern __shared__ char sm[];
    const int z = blockIdx.z;
    const __nv_bfloat16* Bh = (z == 0) ? wqh : (z == 1) ? wkh : wvh;
    const __nv_bfloat16* Bl = (z == 0) ? wql : (z == 1) ? wkl : wvl;
    __nv_bfloat16* Ch = (z == 0) ? qh : (z == 1) ? kh : vh;
    __nv_bfloat16* Cl = (z == 0) ? ql : (z == 1) ? kl : vl;
    gemm_body<true>(xh, xl, Bh, Bl, nullptr, Ch, Cl,
                    blockIdx.y * 128, blockIdx.x * 128, sm);
}

__global__ __launch_bounds__(256)
void gemm_out(const __nv_bfloat16* __restrict__ Ah, const __nv_bfloat16* __restrict__ Al,
              const __nv_bfloat16* __restrict__ Bh, const __nv_bfloat16* __restrict__ Bl,
              float* __restrict__ C)
{
    extern __shared__ char sm[];
    gemm_body<false>(Ah, Al, Bh, Bl, C, nullptr, nullptr,
                     blockIdx.y * 128, blockIdx.x * 128, sm);
}

// ---------------- lambda ----------------
__global__ void lambda_kernel(const float* __restrict__ lq1, const float* __restrict__ lk1,
                              const float* __restrict__ lq2, const float* __restrict__ lk2)
{
    const int lane = threadIdx.x;
    float a = lq1[lane] * lk1[lane];
    float b = lq2[lane] * lk2[lane];
#pragma unroll
    for (int off = 16; off; off >>= 1) {
        a += __shfl_xor_sync(0xffffffffu, a, off);
        b += __shfl_xor_sync(0xffffffffu, b, off);
    }
    if (lane == 0) g_lambda = __expf(a) - __expf(b) + LAMBDA_INIT_C;
}

// ============================================================================
// Fused tensor-core flash: one CTA = (q-tile of 128 rows) x (value-head pair).
// Both heads' S/PV computed with shared V tile; epilogue does the diff,
// RMSNorm(64), gamma, (1-lambda_init), and bf16-split store to (ah, al).
// ============================================================================
#define QT 128
#define KT 64
#define VSTR 144
#define FQ(hd2, sp)     (((hd2) * 2 + (sp)) * 10240)                       // 4 x 10240
#define FK(st, hd2, sp) (40960 + ((((st) * 2 + (hd2)) * 2) + (sp)) * 5120) // 8 x 5120
#define FV(st, sp)      (81920 + ((st) * 2 + (sp)) * 9216)                 // 4 x 9216
#define FSMEM 118784

__global__ __launch_bounds__(256, 1)
void diff_flash_fused(const __nv_bfloat16* __restrict__ Qh, const __nv_bfloat16* __restrict__ Ql,
                      const __nv_bfloat16* __restrict__ Kh, const __nv_bfloat16* __restrict__ Kl,
                      const __nv_bfloat16* __restrict__ Vh, const __nv_bfloat16* __restrict__ Vl,
                      const float* __restrict__ gamma,
                      __nv_bfloat16* __restrict__ Ah, __nv_bfloat16* __restrict__ Al)
{
    extern __shared__ char sm[];
    const uint32_t sb = smem_u32(sm);
    const int tid  = threadIdx.x;
    const int lane = tid & 31;
    const int wq   = tid >> 5;
    const int hv   = blockIdx.y;                  // value head 0..15
    const int it   = gridDim.x - 1 - blockIdx.x;
    const int qbase = it * QT;
    const int coff  = hv * DV;                    // Q/K cols hv*64 .. +63 (two heads)
    const int njt   = 2 * it + 2;

    // ---- prologue: Q (both heads, both splits)
#pragma unroll
    for (int a = 0; a < 4; ++a) {                 // a = hd2*2+sp
        const __nv_bfloat16* src = (a & 1) ? Ql : Qh;
        const int co = coff + (a >> 1) * HD;
#pragma unroll
        for (int i = 0; i < 2; ++i) {
            int seg = tid + i * 256;
            int row = seg >> 2, c = (seg & 3) * 16;
            CP_ASYNC16(sb + FQ(a >> 1, a & 1) + row * GSTR + c,
                       (const char*)(src + (size_t)(qbase + row) * EDIM + co) + c);
        }
    }
    CP_COMMIT();

    auto load_kv = [&](int jt, int st) {
        {   // K: 4 arrays x 256 segs -> 1 seg/thread/array
            int row = tid >> 2, c = (tid & 3) * 16;
#pragma unroll
            for (int a = 0; a < 4; ++a) {
                const __nv_bfloat16* src = (a & 1) ? Kl : Kh;
                const int co = coff + (a >> 1) * HD;
                CP_ASYNC16(sb + FK(st, a >> 1, a & 1) + row * GSTR + c,
                           (const char*)(src + (size_t)(jt * KT + row) * EDIM + co) + c);
            }
        }
#pragma unroll
        for (int sp = 0; sp < 2; ++sp) {          // V: 512 segs/split -> 2/thread
            const __nv_bfloat16* src = sp ? Vl : Vh;
#pragma unroll
            for (int i = 0; i < 2; ++i) {
                int seg = tid + i * 256;
                int row = seg >> 3, c = (seg & 7) * 16;
                CP_ASYNC16(sb + FV(st, sp) + row * VSTR + c,
                           (const char*)(src + (size_t)(jt * KT + row) * EDIM + coff) + c);
            }
        }
        CP_COMMIT();
    };
    load_kv(0, 0);
    load_kv(1, 1);

    // ---- Q fragments for both heads
    uint32_t qfh[2][2][4], qfl[2][2][4];          // [head][ks][4]
    CP_WAIT2();
    __syncthreads();
    {
        const uint32_t oa = (uint32_t)((wq * 16 + (lane & 15)) * GSTR + (lane >> 4) * 16);
#pragma unroll
        for (int hd2 = 0; hd2 < 2; ++hd2)
#pragma unroll
            for (int ks = 0; ks < 2; ++ks) {
                ldm_x4(qfh[hd2][ks], sb + FQ(hd2, 0) + oa + ks * 32);
                ldm_x4(qfl[hd2][ks], sb + FQ(hd2, 1) + oa + ks * 32);
            }
    }

    float ofa[8][4], ofb[8][4];
#pragma unroll
    for (int nf = 0; nf < 8; ++nf)
#pragma unroll
        for (int e = 0; e < 4; ++e) { ofa[nf][e] = 0.f; ofb[nf][e] = 0.f; }
    float la0 = 0.f, la1 = 0.f, lb0 = 0.f, lb1 = 0.f;

    const int row0 = qbase + wq * 16 + (lane >> 2);
    const int row1 = row0 + 8;
    const int rmax = qbase + wq * 16 + 15;

    for (int jt = 0; jt < njt; ++jt) {
        CP_WAIT1();
        __syncthreads();
        const int st = jt & 1;

        if ((jt * KT) <= rmax) {
            const bool need_mask = (jt * KT + KT - 1) > (qbase + wq * 16);
            const uint32_t kb = (uint32_t)((lane & 7) + (lane >> 4) * 8) * GSTR
                                + ((lane >> 3) & 1) * 16;
            const uint32_t vb = (uint32_t)((lane & 7) + ((lane >> 3) & 1) * 8) * VSTR
                                + (lane >> 4) * 16;

#pragma unroll
            for (int hd2 = 0; hd2 < 2; ++hd2) {
                float sf[8][4];
#pragma unroll
                for (int nf = 0; nf < 8; ++nf)
#pragma unroll
                    for (int e = 0; e < 4; ++e) sf[nf][e] = 0.f;
#pragma unroll
                for (int ks = 0; ks < 2; ++ks) {
#pragma unroll
                    for (int nb = 0; nb < 4; ++nb) {
                        uint32_t bh4[4], bl4[4];
                        const uint32_t ob = kb + nb * (16 * GSTR) + ks * 32;
                        ldm_x4(bh4, sb + FK(st, hd2, 0) + ob);
                        ldm_x4(bl4, sb + FK(st, hd2, 1) + ob);
                        hmma(sf[2 * nb],     qfh[hd2][ks], bh4);
                        hmma(sf[2 * nb + 1], qfh[hd2][ks], bh4 + 2);
                        hmma(sf[2 * nb],     qfh[hd2][ks], bl4);
                        hmma(sf[2 * nb + 1], qfh[hd2][ks], bl4 + 2);
                        hmma(sf[2 * nb],     qfl[hd2][ks], bh4);
                        hmma(sf[2 * nb + 1], qfl[hd2][ks], bh4 + 2);
                    }
                }

                float ls0 = 0.f, ls1 = 0.f;
                if (need_mask) {
#pragma unroll
                    for (int nf = 0; nf < 8; ++nf) {
                        const int col = jt * KT + nf * 8 + (lane & 3) * 2;
                        sf[nf][0] = (col     <= row0) ? fexps(sf[nf][0]) : 0.f;
                        sf[nf][1] = (col + 1 <= row0) ? fexps(sf[nf][1]) : 0.f;
                        sf[nf][2] = (col     <= row1) ? fexps(sf[nf][2]) : 0.f;
                        sf[nf][3] = (col + 1 <= row1) ? fexps(sf[nf][3]) : 0.f;
                        ls0 += sf[nf][0] + sf[nf][1];
                        ls1 += sf[nf][2] + sf[nf][3];
                    }
                } else {
#pragma unroll
                    for (int nf = 0; nf < 8; ++nf) {
                        sf[nf][0] = fexps(sf[nf][0]);
                        sf[nf][1] = fexps(sf[nf][1]);
                        sf[nf][2] = fexps(sf[nf][2]);
                        sf[nf][3] = fexps(sf[nf][3]);
                        ls0 += sf[nf][0] + sf[nf][1];
                        ls1 += sf[nf][2] + sf[nf][3];
                    }
                }
                if (hd2 == 0) { la0 += ls0; la1 += ls1; }
                else          { lb0 += ls0; lb1 += ls1; }

                uint32_t pha[4][4], pla[4][4];
#pragma unroll
                for (int kf = 0; kf < 4; ++kf) {
                    pha[kf][0] = packsplit(sf[2 * kf][0],     sf[2 * kf][1],     pla[kf][0]);
                    pha[kf][1] = packsplit(sf[2 * kf][2],     sf[2 * kf][3],     pla[kf][1]);
                    pha[kf][2] = packsplit(sf[2 * kf + 1][0], sf[2 * kf + 1][1], pla[kf][2]);
                    pha[kf][3] = packsplit(sf[2 * kf + 1][2], sf[2 * kf + 1][3], pla[kf][3]);
                }

                float (*of)[4] = hd2 ? ofb : ofa;
#pragma unroll
                for (int kf = 0; kf < 4; ++kf) {
#pragma unroll
                    for (int nb = 0; nb < 4; ++nb) {
                        uint32_t vh4[4], vl4[4];
                        const uint32_t ov = vb + kf * (16 * VSTR) + nb * 32;
                        ldm_x4_t(vh4, sb + FV(st, 0) + ov);
                        ldm_x4_t(vl4, sb + FV(st, 1) + ov);
                        hmma(of[2 * nb],     pha[kf], vh4);
                        hmma(of[2 * nb + 1], pha[kf], vh4 + 2);
                        hmma(of[2 * nb],     pha[kf], vl4);
                        hmma(of[2 * nb + 1], pha[kf], vl4 + 2);
                        hmma(of[2 * nb],     pla[kf], vh4);
                        hmma(of[2 * nb + 1], pla[kf], vh4 + 2);
                    }
                }
            }
        }

        __syncthreads();
        if (jt + 2 < njt) load_kv(jt + 2, st);
    }

    // ---- epilogue: diff, RMSNorm(64), gamma, scale, bf16-split store
    auto qsum = [](float v) {
        v += __shfl_xor_sync(0xffffffffu, v, 1);
        v += __shfl_xor_sync(0xffffffffu, v, 2);
        return v;
    };
    const float ia0 = 1.f / qsum(la0), ia1 = 1.f / qsum(la1);
    const float lam = g_lambda;
    const float ib0 = lam / qsum(lb0), ib1 = lam / qsum(lb1);

    float d[8][4];
    float ss0 = 0.f, ss1 = 0.f;
#pragma unroll
    for (int nf = 0; nf < 8; ++nf) {
        d[nf][0] = ofa[nf][0] * ia0 - ofb[nf][0] * ib0;
        d[nf][1] = ofa[nf][1] * ia0 - ofb[nf][1] * ib0;
        d[nf][2] = ofa[nf][2] * ia1 - ofb[nf][2] * ib1;
        d[nf][3] = ofa[nf][3] * ia1 - ofb[nf][3] * ib1;
        ss0 += d[nf][0] * d[nf][0] + d[nf][1] * d[nf][1];
        ss1 += d[nf][2] * d[nf][2] + d[nf][3] * d[nf][3];
    }
    ss0 = qsum(ss0); ss1 = qsum(ss1);
    const float w  = 1.0f - LAMBDA_INIT_C;
    const float r0 = rsqrtf(ss0 * (1.f / 64.f) + 1e-5f) * w;
    const float r1 = rsqrtf(ss1 * (1.f / 64.f) + 1e-5f) * w;

#pragma unroll
    for (int nf = 0; nf < 8; ++nf) {
        const int col = nf * 8 + (lane & 3) * 2;
        const float g0 = gamma[col], g1 = gamma[col + 1];
        store_split2(Ah, Al, (size_t)row0 * EDIM + coff + col,
                     d[nf][0] * g0 * r0, d[nf][1] * g1 * r0);
        store_split2(Ah, Al, (size_t)row1 * EDIM + coff + col,
                     d[nf][2] * g0 * r1, d[nf][3] * g1 * r1);
    }
}

// ---------------- launch ----------------
extern "C" void kernel_launch(void* const* d_in, const int* in_sizes, int n_in,
                              void* d_out, int out_size)
{
    const float* x   = (const float*)d_in[0];
    const float* Wq  = (const float*)d_in[1];
    const float* Wk  = (const float*)d_in[2];
    const float* Wv  = (const float*)d_in[3];
    const float* Wo  = (const float*)d_in[4];
    const float* lq1 = (const float*)d_in[5];
    const float* lk1 = (const float*)d_in[6];
    const float* lq2 = (const float*)d_in[7];
    const float* lk2 = (const float*)d_in[8];
    const float* gam = (const float*)d_in[9];
    float* out = (float*)d_out;

    __nv_bfloat16 *xh, *xl, *wqh, *wql, *wkh, *wkl, *wvh, *wvl, *woh, *wol, *ah, *al;
    __nv_bfloat16 *qh, *ql, *kh, *kl, *vh, *vl;
    cudaGetSymbolAddress((void**)&xh, g_xh);   cudaGetSymbolAddress((void**)&xl, g_xl);
    cudaGetSymbolAddress((void**)&wqh, g_wqh); cudaGetSymbolAddress((void**)&wql, g_wql);
    cudaGetSymbolAddress((void**)&wkh, g_wkh); cudaGetSymbolAddress((void**)&wkl, g_wkl);
    cudaGetSymbolAddress((void**)&wvh, g_wvh); cudaGetSymbolAddress((void**)&wvl, g_wvl);
    cudaGetSymbolAddress((void**)&woh, g_woh); cudaGetSymbolAddress((void**)&wol, g_wol);
    cudaGetSymbolAddress((void**)&ah, g_ah);   cudaGetSymbolAddress((void**)&al, g_al);
    cudaGetSymbolAddress((void**)&qh, g_qh);   cudaGetSymbolAddress((void**)&ql, g_ql);
    cudaGetSymbolAddress((void**)&kh, g_kh);   cudaGetSymbolAddress((void**)&kl, g_kl);
    cudaGetSymbolAddress((void**)&vh, g_vh);   cudaGetSymbolAddress((void**)&vl, g_vl);

    cudaFuncSetAttribute(gemm_qkv, cudaFuncAttributeMaxDynamicSharedMemorySize, GSMEM);
    cudaFuncSetAttribute(gemm_out, cudaFuncAttributeMaxDynamicSharedMemorySize, GSMEM);
    cudaFuncSetAttribute(diff_flash_fused, cudaFuncAttributeMaxDynamicSharedMemorySize, FSMEM);

    const int nx = TSEQ * EDIM, nw = EDIM * EDIM;
    split_kernel<<<nx / 1024, 256>>>(x,  xh,  xl);
    split_kernel<<<nw / 1024, 256>>>(Wq, wqh, wql);
    split_kernel<<<nw / 1024, 256>>>(Wk, wkh, wkl);
    split_kernel<<<nw / 1024, 256>>>(Wv, wvh, wvl);
    split_kernel<<<nw / 1024, 256>>>(Wo, woh, wol);

    lambda_kernel<<<1, 32>>>(lq1, lk1, lq2, lk2);

    dim3 gq(EDIM / 128, TSEQ / 128, 3);
    gemm_qkv<<<gq, 256, GSMEM>>>(xh, xl, wqh, wql, wkh, wkl, wvh, wvl,
                                 qh, ql, kh, kl, vh, vl);

    dim3 fg(TSEQ / QT, NH);
    diff_flash_fused<<<fg, 256, FSMEM>>>(qh, ql, kh, kl, vh, vl, gam, ah, al);

    dim3 gg(EDIM / 128, TSEQ / 128);
    gemm_out<<<gg, 256, GSMEM>>>(ah, al, woh, wol, out);
}

// round 15
// speedup vs baseline: 1.0502x; 1.0502x over previous
#include <cuda_runtime.h>
#include <cuda_bf16.h>
#include <cstdint>

#define TSEQ 2048
#define EDIM 1024
#define HD   32
#define DV   64
#define NQH  32
#define NH   16
#define LAMBDA_INIT_C 0.47071301834358415f

// ---------------- scratch ----------------
__device__ float g_Ohead[NQH * TSEQ * DV];
__device__ float g_lambda;
__device__ __nv_bfloat16 g_xh[TSEQ * EDIM],  g_xl[TSEQ * EDIM];
__device__ __nv_bfloat16 g_wqh[EDIM * EDIM], g_wql[EDIM * EDIM];
__device__ __nv_bfloat16 g_wkh[EDIM * EDIM], g_wkl[EDIM * EDIM];
__device__ __nv_bfloat16 g_wvh[EDIM * EDIM], g_wvl[EDIM * EDIM];
__device__ __nv_bfloat16 g_woh[EDIM * EDIM], g_wol[EDIM * EDIM];
__device__ __nv_bfloat16 g_ah[TSEQ * EDIM],  g_al[TSEQ * EDIM];
__device__ __nv_bfloat16 g_qh[TSEQ * EDIM],  g_ql[TSEQ * EDIM];
__device__ __nv_bfloat16 g_kh[TSEQ * EDIM],  g_kl[TSEQ * EDIM];
__device__ __nv_bfloat16 g_vh[TSEQ * EDIM],  g_vl[TSEQ * EDIM];

// ---------------- helpers ----------------
__device__ __forceinline__ uint32_t smem_u32(const void* p) {
    uint32_t a;
    asm("{ .reg .u64 t; cvta.to.shared.u64 t, %1; cvt.u32.u64 %0, t; }" : "=r"(a) : "l"(p));
    return a;
}
__device__ __forceinline__ void ldm_x4(uint32_t* r, uint32_t addr) {
    asm volatile("ldmatrix.sync.aligned.m8n8.x4.shared.b16 {%0,%1,%2,%3}, [%4];"
                 : "=r"(r[0]), "=r"(r[1]), "=r"(r[2]), "=r"(r[3]) : "r"(addr));
}
__device__ __forceinline__ void ldm_x4_t(uint32_t* r, uint32_t addr) {
    asm volatile("ldmatrix.sync.aligned.m8n8.x4.trans.shared.b16 {%0,%1,%2,%3}, [%4];"
                 : "=r"(r[0]), "=r"(r[1]), "=r"(r[2]), "=r"(r[3]) : "r"(addr));
}
__device__ __forceinline__ void hmma(float* d, const uint32_t* a, const uint32_t* b) {
    asm volatile("mma.sync.aligned.m16n8k16.row.col.f32.bf16.bf16.f32 "
                 "{%0,%1,%2,%3}, {%4,%5,%6,%7}, {%8,%9}, {%0,%1,%2,%3};"
                 : "+f"(d[0]), "+f"(d[1]), "+f"(d[2]), "+f"(d[3])
                 : "r"(a[0]), "r"(a[1]), "r"(a[2]), "r"(a[3]), "r"(b[0]), "r"(b[1]));
}
#define CP_ASYNC16(s, g) asm volatile("cp.async.cg.shared.global [%0], [%1], 16;" :: "r"(s), "l"(g))
#define CP_COMMIT()      asm volatile("cp.async.commit_group;" ::: "memory")
#define CP_WAIT1()       asm volatile("cp.async.wait_group 1;" ::: "memory")
#define CP_WAIT2()       asm volatile("cp.async.wait_group 2;" ::: "memory")

// 2^(x*SCL2E), SCL2E = (1/sqrt(32))*log2(e)
__device__ __forceinline__ float fexps(float x) {
    const float SCL2E = 0.25506943387767815f;
    float y = fmaf(x, SCL2E, 12582912.0f);
    int   n = __float_as_int(y) - 0x4B400000;
    float r = fmaf(x, SCL2E, -(y - 12582912.0f));
    float t = 0.00133335581f;
    t = fmaf(t, r, 0.00961812910f);
    t = fmaf(t, r, 0.05550410866f);
    t = fmaf(t, r, 0.24022650695f);
    t = fmaf(t, r, 0.69314718056f);
    t = fmaf(t, r, 1.0f);
    return __int_as_float(__float_as_int(t) + (n << 23));
}
__device__ __forceinline__ uint32_t packsplit(float a, float b, uint32_t& lo) {
    __nv_bfloat16 ha = __float2bfloat16(a), hb = __float2bfloat16(b);
    __nv_bfloat162 l2 = __halves2bfloat162(
        __float2bfloat16(a - __bfloat162float(ha)),
        __float2bfloat16(b - __bfloat162float(hb)));
    lo = *(uint32_t*)&l2;
    __nv_bfloat162 h2 = __halves2bfloat162(ha, hb);
    return *(uint32_t*)&h2;
}
__device__ __forceinline__ void store_split2(__nv_bfloat16* H, __nv_bfloat16* L,
                                             size_t i, float a, float b) {
    __nv_bfloat16 ha = __float2bfloat16(a), hb = __float2bfloat16(b);
    *(__nv_bfloat162*)(H + i) = __halves2bfloat162(ha, hb);
    *(__nv_bfloat162*)(L + i) = __halves2bfloat162(
        __float2bfloat16(a - __bfloat162float(ha)),
        __float2bfloat16(b - __bfloat162float(hb)));
}

// ---------------- fp32 -> (hi, lo) bf16 splits ----------------
__global__ __launch_bounds__(256)
void split_kernel(const float* __restrict__ x, __nv_bfloat16* __restrict__ hi,
                  __nv_bfloat16* __restrict__ lo)
{
    int i = (blockIdx.x * 256 + threadIdx.x) * 4;
    float4 v = *(const float4*)(x + i);
    store_split2(hi, lo, i,     v.x, v.y);
    store_split2(hi, lo, i + 2, v.z, v.w);
}

// all four weight splits in one launch (z selects the matrix)
__global__ __launch_bounds__(256)
void split_w4(const float* __restrict__ Wq, const float* __restrict__ Wk,
              const float* __restrict__ Wv, const float* __restrict__ Wo,
              __nv_bfloat16* __restrict__ qh, __nv_bfloat16* __restrict__ ql,
              __nv_bfloat16* __restrict__ kh, __nv_bfloat16* __restrict__ kl,
              __nv_bfloat16* __restrict__ vh, __nv_bfloat16* __restrict__ vl,
              __nv_bfloat16* __restrict__ oh, __nv_bfloat16* __restrict__ ol)
{
    const int z = blockIdx.z;
    const float* x = (z == 0) ? Wq : (z == 1) ? Wk : (z == 2) ? Wv : Wo;
    __nv_bfloat16* hi = (z == 0) ? qh : (z == 1) ? kh : (z == 2) ? vh : oh;
    __nv_bfloat16* lo = (z == 0) ? ql : (z == 1) ? kl : (z == 2) ? vl : ol;
    int i = (blockIdx.x * 256 + threadIdx.x) * 4;
    float4 v = *(const float4*)(x + i);
    store_split2(hi, lo, i,     v.x, v.y);
    store_split2(hi, lo, i + 2, v.z, v.w);
}

// ============================================================================
// HMMA bf16x3 GEMM body (NT), 128x128 tile, BK=32, 3-stage cp.async.
// ============================================================================
#define GSTR   80
#define GTILEB (128 * GSTR)
#define GSTAGE (4 * GTILEB)
#define GSMEM  (3 * GSTAGE)

template<bool BF16OUT>
__device__ __forceinline__
void gemm_body(const __nv_bfloat16* __restrict__ Ah, const __nv_bfloat16* __restrict__ Al,
               const __nv_bfloat16* __restrict__ Bh, const __nv_bfloat16* __restrict__ Bl,
               float* __restrict__ C, __nv_bfloat16* __restrict__ Ch,
               __nv_bfloat16* __restrict__ Cl, int bm, int bn, char* sm)
{
    const uint32_t sb = smem_u32(sm);
    const int tid  = threadIdx.x;
    const int lane = tid & 31;
    const int wid  = tid >> 5;
    const int wm   = wid >> 2;
    const int wn   = wid & 3;

    const int lt = tid >> 6;
    const int u  = tid & 63;
    const int lrow0 = u >> 2;
    const int lcseg = (u & 3) * 16;
    const char* gsrc;
    {
        const char* s0 = (const char*)(Ah + (size_t)bm * EDIM);
        const char* s1 = (const char*)(Al + (size_t)bm * EDIM);
        const char* s2 = (const char*)(Bh + (size_t)bn * EDIM);
        const char* s3 = (const char*)(Bl + (size_t)bn * EDIM);
        gsrc = (lt == 0) ? s0 : (lt == 1) ? s1 : (lt == 2) ? s2 : s3;
    }
    const uint32_t sdst0 = sb + lt * GTILEB + lrow0 * GSTR + lcseg;

    auto issue = [&](int c, int st) {
        const char* g = gsrc + (size_t)lrow0 * 2048 + (size_t)c * 64 + lcseg;
        uint32_t s = sdst0 + st * GSTAGE;
#pragma unroll
        for (int i = 0; i < 8; ++i)
            CP_ASYNC16(s + i * 16 * GSTR, g + (size_t)i * 16 * 2048);
        CP_COMMIT();
    };

    const uint32_t offA = (uint32_t)((wm * 64 + (lane & 15)) * GSTR + (lane >> 4) * 16);
    const uint32_t offB = (uint32_t)((wn * 32 + (lane & 7) + (lane >> 4) * 8) * GSTR
                                     + ((lane >> 3) & 1) * 16);

    float acc[4][4][4];
#pragma unroll
    for (int i = 0; i < 4; ++i)
#pragma unroll
        for (int j = 0; j < 4; ++j)
#pragma unroll
            for (int k = 0; k < 4; ++k) acc[i][j][k] = 0.f;

    issue(0, 0);
    issue(1, 1);

    for (int c = 0; c < 32; ++c) {
        CP_WAIT1();
        __syncthreads();
        if (c + 2 < 32) issue(c + 2, (c + 2) % 3);

        const uint32_t stb = sb + (c % 3) * GSTAGE;
        const uint32_t tAh = stb, tAl = stb + GTILEB;
        const uint32_t tBh = stb + 2 * GTILEB, tBl = stb + 3 * GTILEB;

#pragma unroll
        for (int ks = 0; ks < 2; ++ks) {
            const uint32_t ko = ks * 32;
            uint32_t ah[4][4], al[4][4], bh[2][4], bl[2][4];
#pragma unroll
            for (int mf = 0; mf < 4; ++mf) {
                ldm_x4(ah[mf], tAh + offA + mf * (16 * GSTR) + ko);
                ldm_x4(al[mf], tAl + offA + mf * (16 * GSTR) + ko);
            }
#pragma unroll
            for (int nf = 0; nf < 2; ++nf) {
                ldm_x4(bh[nf], tBh + offB + nf * (16 * GSTR) + ko);
                ldm_x4(bl[nf], tBl + offB + nf * (16 * GSTR) + ko);
            }
#pragma unroll
            for (int mf = 0; mf < 4; ++mf)
#pragma unroll
                for (int nf = 0; nf < 4; ++nf) {
                    const uint32_t* BH = &bh[nf >> 1][(nf & 1) * 2];
                    const uint32_t* BL = &bl[nf >> 1][(nf & 1) * 2];
                    hmma(acc[mf][nf], ah[mf], BH);
                    hmma(acc[mf][nf], ah[mf], BL);
                    hmma(acc[mf][nf], al[mf], BH);
                }
        }
        __syncthreads();
    }

    const int mrow = bm + wm * 64 + (lane >> 2);
    const int ncol = bn + wn * 32 + (lane & 3) * 2;
#pragma unroll
    for (int mf = 0; mf < 4; ++mf)
#pragma unroll
        for (int nf = 0; nf < 4; ++nf) {
            size_t i0 = (size_t)(mrow + mf * 16) * EDIM + ncol + nf * 8;
            size_t i1 = i0 + 8 * EDIM;
            if (BF16OUT) {
                store_split2(Ch, Cl, i0, acc[mf][nf][0], acc[mf][nf][1]);
                store_split2(Ch, Cl, i1, acc[mf][nf][2], acc[mf][nf][3]);
            } else {
                *(float2*)(C + i0) = make_float2(acc[mf][nf][0], acc[mf][nf][1]);
                *(float2*)(C + i1) = make_float2(acc[mf][nf][2], acc[mf][nf][3]);
            }
        }
}

// Q/K/V projections in ONE launch (grid.z selects weight & destination)
__global__ __launch_bounds__(256)
void gemm_qkv(const __nv_bfloat16* __restrict__ xh, const __nv_bfloat16* __restrict__ xl,
              const __nv_bfloat16* __restrict__ wqh, const __nv_bfloat16* __restrict__ wql,
              const __nv_bfloat16* __restrict__ wkh, const __nv_bfloat16* __restrict__ wkl,
              const __nv_bfloat16* __restrict__ wvh, const __nv_bfloat16* __restrict__ wvl,
              __nv_bfloat16* __restrict__ qh, __nv_bfloat16* __restrict__ ql,
              __nv_bfloat16* __restrict__ kh, __nv_bfloat16* __restrict__ kl,
              __nv_bfloat16* __restrict__ vh, __nv_bfloat16* __restrict__ vl)
{
    extern __shared__ char sm[];
    const int z = blockIdx.z;
    const __nv_bfloat16* Bh = (z == 0) ? wqh : (z == 1) ? wkh : wvh;
    const __nv_bfloat16* Bl = (z == 0) ? wql : (z == 1) ? wkl : wvl;
    __nv_bfloat16* Ch = (z == 0) ? qh : (z == 1) ? kh : vh;
    __nv_bfloat16* Cl = (z == 0) ? ql : (z == 1) ? kl : vl;
    gemm_body<true>(xh, xl, Bh, Bl, nullptr, Ch, Cl,
                    blockIdx.y * 128, blockIdx.x * 128, sm);
}

__global__ __launch_bounds__(256)
void gemm_out(const __nv_bfloat16* __restrict__ Ah, const __nv_bfloat16* __restrict__ Al,
              const __nv_bfloat16* __restrict__ Bh, const __nv_bfloat16* __restrict__ Bl,
              float* __restrict__ C)
{
    extern __shared__ char sm[];
    gemm_body<false>(Ah, Al, Bh, Bl, C, nullptr, nullptr,
                     blockIdx.y * 128, blockIdx.x * 128, sm);
}

// ---------------- lambda ----------------
__global__ void lambda_kernel(const float* __restrict__ lq1, const float* __restrict__ lk1,
                              const float* __restrict__ lq2, const float* __restrict__ lk2)
{
    const int lane = threadIdx.x;
    float a = lq1[lane] * lk1[lane];
    float b = lq2[lane] * lk2[lane];
#pragma unroll
    for (int off = 16; off; off >>= 1) {
        a += __shfl_xor_sync(0xffffffffu, a, off);
        b += __shfl_xor_sync(0xffffffffu, b, off);
    }
    if (lane == 0) g_lambda = __expf(a) - __expf(b) + LAMBDA_INIT_C;
}

// ============================================================================
// Tensor-core flash (R13 config: 512 CTAs, one head per CTA). Q tile 128,
// KV tile 64. S=QhKh+QhKl+QlKh; P register-repacked; O+=PhVh+PhVl+PlVh.
// ============================================================================
#define QT 128
#define KT 64
#define VSTR 144
#define FQ(sp)        ((sp) * 10240)
#define FK(st, sp)    (20480 + (st) * 10240 + (sp) * 5120)
#define FV(st, sp)    (40960 + (st) * 18432 + (sp) * 9216)
#define FSMEM 77824

__global__ __launch_bounds__(256)
void diff_flash_tc(const __nv_bfloat16* __restrict__ Qh, const __nv_bfloat16* __restrict__ Ql,
                   const __nv_bfloat16* __restrict__ Kh, const __nv_bfloat16* __restrict__ Kl,
                   const __nv_bfloat16* __restrict__ Vh, const __nv_bfloat16* __restrict__ Vl,
                   float* __restrict__ O)
{
    extern __shared__ char sm[];
    const uint32_t sb = smem_u32(sm);
    const int tid  = threadIdx.x;
    const int lane = tid & 31;
    const int wq   = tid >> 5;
    const int h    = blockIdx.y;
    const int it   = gridDim.x - 1 - blockIdx.x;
    const int qbase = it * QT;
    const int qoff  = h * HD;
    const int voff  = (h >> 1) * DV;
    const int njt   = 2 * it + 2;

#pragma unroll
    for (int sp = 0; sp < 2; ++sp) {
        const __nv_bfloat16* src = sp ? Ql : Qh;
#pragma unroll
        for (int i = 0; i < 2; ++i) {
            int seg = tid + i * 256;
            int row = seg >> 2, c = (seg & 3) * 16;
            CP_ASYNC16(sb + FQ(sp) + row * GSTR + c,
                       (const char*)(src + (size_t)(qbase + row) * EDIM + qoff) + c);
        }
    }
    CP_COMMIT();

    auto load_kv = [&](int jt, int st) {
        {
            int row = tid >> 2, c = (tid & 3) * 16;
            CP_ASYNC16(sb + FK(st, 0) + row * GSTR + c,
                       (const char*)(Kh + (size_t)(jt * KT + row) * EDIM + qoff) + c);
            CP_ASYNC16(sb + FK(st, 1) + row * GSTR + c,
                       (const char*)(Kl + (size_t)(jt * KT + row) * EDIM + qoff) + c);
        }
#pragma unroll
        for (int i = 0; i < 2; ++i) {
            int seg = tid + i * 256;
            int row = seg >> 3, c = (seg & 7) * 16;
            CP_ASYNC16(sb + FV(st, 0) + row * VSTR + c,
                       (const char*)(Vh + (size_t)(jt * KT + row) * EDIM + voff) + c);
            CP_ASYNC16(sb + FV(st, 1) + row * VSTR + c,
                       (const char*)(Vl + (size_t)(jt * KT + row) * EDIM + voff) + c);
        }
        CP_COMMIT();
    };
    load_kv(0, 0);
    load_kv(1, 1);

    uint32_t qfh[2][4], qfl[2][4];
    CP_WAIT2();
    __syncthreads();
    {
        const uint32_t oa = (uint32_t)((wq * 16 + (lane & 15)) * GSTR + (lane >> 4) * 16);
#pragma unroll
        for (int ks = 0; ks < 2; ++ks) {
            ldm_x4(qfh[ks], sb + FQ(0) + oa + ks * 32);
            ldm_x4(qfl[ks], sb + FQ(1) + oa + ks * 32);
        }
    }

    float of[8][4];
#pragma unroll
    for (int nf = 0; nf < 8; ++nf)
#pragma unroll
        for (int e = 0; e < 4; ++e) of[nf][e] = 0.f;
    float l0 = 0.f, l1 = 0.f;

    const int row0 = qbase + wq * 16 + (lane >> 2);
    const int row1 = row0 + 8;
    const int rmax = qbase + wq * 16 + 15;

    for (int jt = 0; jt < njt; ++jt) {
        CP_WAIT1();
        __syncthreads();
        const int st = jt & 1;

        if ((jt * KT) <= rmax) {
            float sf[8][4];
#pragma unroll
            for (int nf = 0; nf < 8; ++nf)
#pragma unroll
                for (int e = 0; e < 4; ++e) sf[nf][e] = 0.f;
            const uint32_t kb = (uint32_t)((lane & 7) + (lane >> 4) * 8) * GSTR
                                + ((lane >> 3) & 1) * 16;
#pragma unroll
            for (int ks = 0; ks < 2; ++ks) {
#pragma unroll
                for (int nb = 0; nb < 4; ++nb) {
                    uint32_t bh4[4], bl4[4];
                    const uint32_t ob = kb + nb * (16 * GSTR) + ks * 32;
                    ldm_x4(bh4, sb + FK(st, 0) + ob);
                    ldm_x4(bl4, sb + FK(st, 1) + ob);
                    hmma(sf[2 * nb],     qfh[ks], bh4);
                    hmma(sf[2 * nb + 1], qfh[ks], bh4 + 2);
                    hmma(sf[2 * nb],     qfh[ks], bl4);
                    hmma(sf[2 * nb + 1], qfh[ks], bl4 + 2);
                    hmma(sf[2 * nb],     qfl[ks], bh4);
                    hmma(sf[2 * nb + 1], qfl[ks], bh4 + 2);
                }
            }

            const bool need_mask = (jt * KT + KT - 1) > (qbase + wq * 16);
            if (need_mask) {
#pragma unroll
                for (int nf = 0; nf < 8; ++nf) {
                    const int col = jt * KT + nf * 8 + (lane & 3) * 2;
                    sf[nf][0] = (col     <= row0) ? fexps(sf[nf][0]) : 0.f;
                    sf[nf][1] = (col + 1 <= row0) ? fexps(sf[nf][1]) : 0.f;
                    sf[nf][2] = (col     <= row1) ? fexps(sf[nf][2]) : 0.f;
                    sf[nf][3] = (col + 1 <= row1) ? fexps(sf[nf][3]) : 0.f;
                    l0 += sf[nf][0] + sf[nf][1];
                    l1 += sf[nf][2] + sf[nf][3];
                }
            } else {
#pragma unroll
                for (int nf = 0; nf < 8; ++nf) {
                    sf[nf][0] = fexps(sf[nf][0]);
                    sf[nf][1] = fexps(sf[nf][1]);
                    sf[nf][2] = fexps(sf[nf][2]);
                    sf[nf][3] = fexps(sf[nf][3]);
                    l0 += sf[nf][0] + sf[nf][1];
                    l1 += sf[nf][2] + sf[nf][3];
                }
            }

            uint32_t pha[4][4], pla[4][4];
#pragma unroll
            for (int kf = 0; kf < 4; ++kf) {
                pha[kf][0] = packsplit(sf[2 * kf][0],     sf[2 * kf][1],     pla[kf][0]);
                pha[kf][1] = packsplit(sf[2 * kf][2],     sf[2 * kf][3],     pla[kf][1]);
                pha[kf][2] = packsplit(sf[2 * kf + 1][0], sf[2 * kf + 1][1], pla[kf][2]);
                pha[kf][3] = packsplit(sf[2 * kf + 1][2], sf[2 * kf + 1][3], pla[kf][3]);
            }

            const uint32_t vb = (uint32_t)((lane & 7) + ((lane >> 3) & 1) * 8) * VSTR
                                + (lane >> 4) * 16;
#pragma unroll
            for (int kf = 0; kf < 4; ++kf) {
#pragma unroll
                for (int nb = 0; nb < 4; ++nb) {
                    uint32_t vh4[4], vl4[4];
                    const uint32_t ov = vb + kf * (16 * VSTR) + nb * 32;
                    ldm_x4_t(vh4, sb + FV(st, 0) + ov);
                    ldm_x4_t(vl4, sb + FV(st, 1) + ov);
                    hmma(of[2 * nb],     pha[kf], vh4);
                    hmma(of[2 * nb + 1], pha[kf], vh4 + 2);
                    hmma(of[2 * nb],     pha[kf], vl4);
                    hmma(of[2 * nb + 1], pha[kf], vl4 + 2);
                    hmma(of[2 * nb],     pla[kf], vh4);
                    hmma(of[2 * nb + 1], pla[kf], vh4 + 2);
                }
            }
        }

        __syncthreads();
        if (jt + 2 < njt) load_kv(jt + 2, st);
    }

    float t0 = l0, t1 = l1;
    t0 += __shfl_xor_sync(0xffffffffu, t0, 1);
    t0 += __shfl_xor_sync(0xffffffffu, t0, 2);
    t1 += __shfl_xor_sync(0xffffffffu, t1, 1);
    t1 += __shfl_xor_sync(0xffffffffu, t1, 2);
    const float inv0 = 1.f / t0, inv1 = 1.f / t1;
#pragma unroll
    for (int nf = 0; nf < 8; ++nf) {
        const int col = nf * 8 + (lane & 3) * 2;
        *(float2*)(O + ((size_t)h * TSEQ + row0) * DV + col) =
            make_float2(of[nf][0] * inv0, of[nf][1] * inv0);
        *(float2*)(O + ((size_t)h * TSEQ + row1) * DV + col) =
            make_float2(of[nf][2] * inv1, of[nf][3] * inv1);
    }
}

// ---------------- combine + bf16 split (fused) ----------------
__global__ __launch_bounds__(256)
void combine_split(const float* __restrict__ O, const float* __restrict__ gamma,
                   __nv_bfloat16* __restrict__ Ah, __nv_bfloat16* __restrict__ Al)
{
    const int tid = threadIdx.x, warp = tid >> 5, lane = tid & 31;
    const int g = blockIdx.x * 8 + warp;
    const int t = g >> 4, h = g & 15;
    const float lam = g_lambda, w = 1.0f - LAMBDA_INIT_C;

    const size_t b1 = ((size_t)(2 * h) * TSEQ + t) * DV;
    const size_t b2 = ((size_t)(2 * h + 1) * TSEQ + t) * DV;
    const float o0 = O[b1 + lane]      - lam * O[b2 + lane];
    const float o1 = O[b1 + lane + 32] - lam * O[b2 + lane + 32];

    float ss = o0 * o0 + o1 * o1;
#pragma unroll
    for (int off = 16; off; off >>= 1)
        ss += __shfl_xor_sync(0xffffffffu, ss, off);
    const float r = rsqrtf(ss * (1.f / 64.f) + 1e-5f) * w;

    const float a0 = gamma[lane]      * o0 * r;
    const float a1 = gamma[lane + 32] * o1 * r;
    const size_t i0 = (size_t)t * EDIM + h * DV + lane;
    __nv_bfloat16 h0 = __float2bfloat16(a0), h1 = __float2bfloat16(a1);
    Ah[i0]      = h0;
    Ah[i0 + 32] = h1;
    Al[i0]      = __float2bfloat16(a0 - __bfloat162float(h0));
    Al[i0 + 32] = __float2bfloat16(a1 - __bfloat162float(h1));
}

// ---------------- launch ----------------
extern "C" void kernel_launch(void* const* d_in, const int* in_sizes, int n_in,
                              void* d_out, int out_size)
{
    const float* x   = (const float*)d_in[0];
    const float* Wq  = (const float*)d_in[1];
    const float* Wk  = (const float*)d_in[2];
    const float* Wv  = (const float*)d_in[3];
    const float* Wo  = (const float*)d_in[4];
    const float* lq1 = (const float*)d_in[5];
    const float* lk1 = (const float*)d_in[6];
    const float* lq2 = (const float*)d_in[7];
    const float* lk2 = (const float*)d_in[8];
    const float* gam = (const float*)d_in[9];
    float* out = (float*)d_out;

    float *pO;
    __nv_bfloat16 *xh, *xl, *wqh, *wql, *wkh, *wkl, *wvh, *wvl, *woh, *wol, *ah, *al;
    __nv_bfloat16 *qh, *ql, *kh, *kl, *vh, *vl;
    cudaGetSymbolAddress((void**)&pO, g_Ohead);
    cudaGetSymbolAddress((void**)&xh, g_xh);   cudaGetSymbolAddress((void**)&xl, g_xl);
    cudaGetSymbolAddress((void**)&wqh, g_wqh); cudaGetSymbolAddress((void**)&wql, g_wql);
    cudaGetSymbolAddress((void**)&wkh, g_wkh); cudaGetSymbolAddress((void**)&wkl, g_wkl);
    cudaGetSymbolAddress((void**)&wvh, g_wvh); cudaGetSymbolAddress((void**)&wvl, g_wvl);
    cudaGetSymbolAddress((void**)&woh, g_woh); cudaGetSymbolAddress((void**)&wol, g_wol);
    cudaGetSymbolAddress((void**)&ah, g_ah);   cudaGetSymbolAddress((void**)&al, g_al);
    cudaGetSymbolAddress((void**)&qh, g_qh);   cudaGetSymbolAddress((void**)&ql, g_ql);
    cudaGetSymbolAddress((void**)&kh, g_kh);   cudaGetSymbolAddress((void**)&kl, g_kl);
    cudaGetSymbolAddress((void**)&vh, g_vh);   cudaGetSymbolAddress((void**)&vl, g_vl);

    cudaFuncSetAttribute(gemm_qkv, cudaFuncAttributeMaxDynamicSharedMemorySize, GSMEM);
    cudaFuncSetAttribute(gemm_out, cudaFuncAttributeMaxDynamicSharedMemorySize, GSMEM);
    cudaFuncSetAttribute(diff_flash_tc, cudaFuncAttributeMaxDynamicSharedMemorySize, FSMEM);

    const int nx = TSEQ * EDIM, nw = EDIM * EDIM;
    split_kernel<<<nx / 1024, 256>>>(x, xh, xl);
    dim3 gw(nw / 1024, 1, 4);
    split_w4<<<gw, 256>>>(Wq, Wk, Wv, Wo, wqh, wql, wkh, wkl, wvh, wvl, woh, wol);

    lambda_kernel<<<1, 32>>>(lq1, lk1, lq2, lk2);

    dim3 gq(EDIM / 128, TSEQ / 128, 3);
    gemm_qkv<<<gq, 256, GSMEM>>>(xh, xl, wqh, wql, wkh, wkl, wvh, wvl,
                                 qh, ql, kh, kl, vh, vl);

    dim3 fg(TSEQ / QT, NQH);
    diff_flash_tc<<<fg, 256, FSMEM>>>(qh, ql, kh, kl, vh, vl, pO);

    combine_split<<<(TSEQ * NH) / 8, 256>>>(pO, gam, ah, al);

    dim3 gg(EDIM / 128, TSEQ / 128);
    gemm_out<<<gg, 256, GSMEM>>>(ah, al, woh, wol, out);
}

// round 16
// speedup vs baseline: 1.1020x; 1.0493x over previous
#include <cuda_runtime.h>
#include <cuda_bf16.h>
#include <cstdint>

#define TSEQ 2048
#define EDIM 1024
#define HD   32
#define DV   64
#define NQH  32
#define NH   16
#define LAMBDA_INIT_C 0.47071301834358415f

// ---------------- scratch ----------------
__device__ float g_Ohead[NQH * TSEQ * DV];
__device__ float g_lambda;
__device__ __nv_bfloat16 g_xh[TSEQ * EDIM],  g_xl[TSEQ * EDIM];
__device__ __nv_bfloat16 g_wqh[EDIM * EDIM], g_wql[EDIM * EDIM];
__device__ __nv_bfloat16 g_wkh[EDIM * EDIM], g_wkl[EDIM * EDIM];
__device__ __nv_bfloat16 g_wvh[EDIM * EDIM], g_wvl[EDIM * EDIM];
__device__ __nv_bfloat16 g_woh[EDIM * EDIM], g_wol[EDIM * EDIM];
__device__ __nv_bfloat16 g_ah[TSEQ * EDIM],  g_al[TSEQ * EDIM];
__device__ __nv_bfloat16 g_qh[TSEQ * EDIM],  g_ql[TSEQ * EDIM];
__device__ __nv_bfloat16 g_kh[TSEQ * EDIM],  g_kl[TSEQ * EDIM];
__device__ __nv_bfloat16 g_vh[TSEQ * EDIM],  g_vl[TSEQ * EDIM];

// ---------------- helpers ----------------
__device__ __forceinline__ uint32_t smem_u32(const void* p) {
    uint32_t a;
    asm("{ .reg .u64 t; cvta.to.shared.u64 t, %1; cvt.u32.u64 %0, t; }" : "=r"(a) : "l"(p));
    return a;
}
__device__ __forceinline__ void ldm_x4(uint32_t* r, uint32_t addr) {
    asm volatile("ldmatrix.sync.aligned.m8n8.x4.shared.b16 {%0,%1,%2,%3}, [%4];"
                 : "=r"(r[0]), "=r"(r[1]), "=r"(r[2]), "=r"(r[3]) : "r"(addr));
}
__device__ __forceinline__ void ldm_x4_t(uint32_t* r, uint32_t addr) {
    asm volatile("ldmatrix.sync.aligned.m8n8.x4.trans.shared.b16 {%0,%1,%2,%3}, [%4];"
                 : "=r"(r[0]), "=r"(r[1]), "=r"(r[2]), "=r"(r[3]) : "r"(addr));
}
__device__ __forceinline__ void hmma(float* d, const uint32_t* a, const uint32_t* b) {
    asm volatile("mma.sync.aligned.m16n8k16.row.col.f32.bf16.bf16.f32 "
                 "{%0,%1,%2,%3}, {%4,%5,%6,%7}, {%8,%9}, {%0,%1,%2,%3};"
                 : "+f"(d[0]), "+f"(d[1]), "+f"(d[2]), "+f"(d[3])
                 : "r"(a[0]), "r"(a[1]), "r"(a[2]), "r"(a[3]), "r"(b[0]), "r"(b[1]));
}
#define CP_ASYNC16(s, g) asm volatile("cp.async.cg.shared.global [%0], [%1], 16;" :: "r"(s), "l"(g))
#define CP_COMMIT()      asm volatile("cp.async.commit_group;" ::: "memory")
#define CP_WAIT1()       asm volatile("cp.async.wait_group 1;" ::: "memory")
#define CP_WAIT2()       asm volatile("cp.async.wait_group 2;" ::: "memory")

// 2^(x*SCL2E), SCL2E = (1/sqrt(32))*log2(e)
__device__ __forceinline__ float fexps(float x) {
    const float SCL2E = 0.25506943387767815f;
    float y = fmaf(x, SCL2E, 12582912.0f);
    int   n = __float_as_int(y) - 0x4B400000;
    float r = fmaf(x, SCL2E, -(y - 12582912.0f));
    float t = 0.00133335581f;
    t = fmaf(t, r, 0.00961812910f);
    t = fmaf(t, r, 0.05550410866f);
    t = fmaf(t, r, 0.24022650695f);
    t = fmaf(t, r, 0.69314718056f);
    t = fmaf(t, r, 1.0f);
    return __int_as_float(__float_as_int(t) + (n << 23));
}
__device__ __forceinline__ uint32_t packsplit(float a, float b, uint32_t& lo) {
    __nv_bfloat16 ha = __float2bfloat16(a), hb = __float2bfloat16(b);
    __nv_bfloat162 l2 = __halves2bfloat162(
        __float2bfloat16(a - __bfloat162float(ha)),
        __float2bfloat16(b - __bfloat162float(hb)));
    lo = *(uint32_t*)&l2;
    __nv_bfloat162 h2 = __halves2bfloat162(ha, hb);
    return *(uint32_t*)&h2;
}
__device__ __forceinline__ void store_split2(__nv_bfloat16* H, __nv_bfloat16* L,
                                             size_t i, float a, float b) {
    __nv_bfloat16 ha = __float2bfloat16(a), hb = __float2bfloat16(b);
    *(__nv_bfloat162*)(H + i) = __halves2bfloat162(ha, hb);
    *(__nv_bfloat162*)(L + i) = __halves2bfloat162(
        __float2bfloat16(a - __bfloat162float(ha)),
        __float2bfloat16(b - __bfloat162float(hb)));
}

// ---------------- fp32 -> (hi, lo) bf16 splits ----------------
__global__ __launch_bounds__(256)
void split_kernel(const float* __restrict__ x, __nv_bfloat16* __restrict__ hi,
                  __nv_bfloat16* __restrict__ lo)
{
    int i = (blockIdx.x * 256 + threadIdx.x) * 4;
    float4 v = *(const float4*)(x + i);
    store_split2(hi, lo, i,     v.x, v.y);
    store_split2(hi, lo, i + 2, v.z, v.w);
}

__global__ __launch_bounds__(256)
void split_w4(const float* __restrict__ Wq, const float* __restrict__ Wk,
              const float* __restrict__ Wv, const float* __restrict__ Wo,
              __nv_bfloat16* __restrict__ qh, __nv_bfloat16* __restrict__ ql,
              __nv_bfloat16* __restrict__ kh, __nv_bfloat16* __restrict__ kl,
              __nv_bfloat16* __restrict__ vh, __nv_bfloat16* __restrict__ vl,
              __nv_bfloat16* __restrict__ oh, __nv_bfloat16* __restrict__ ol)
{
    const int z = blockIdx.z;
    const float* x = (z == 0) ? Wq : (z == 1) ? Wk : (z == 2) ? Wv : Wo;
    __nv_bfloat16* hi = (z == 0) ? qh : (z == 1) ? kh : (z == 2) ? vh : oh;
    __nv_bfloat16* lo = (z == 0) ? ql : (z == 1) ? kl : (z == 2) ? vl : ol;
    int i = (blockIdx.x * 256 + threadIdx.x) * 4;
    float4 v = *(const float4*)(x + i);
    store_split2(hi, lo, i,     v.x, v.y);
    store_split2(hi, lo, i + 2, v.z, v.w);
}

// ============================================================================
// HMMA bf16x3 GEMM body (NT), 128x128 tile, BK=32, 2-stage cp.async,
// 2 CTAs/SM (cross-CTA latency hiding instead of a third stage).
// ============================================================================
#define GSTR   80
#define GTILEB (128 * GSTR)
#define GSTAGE (4 * GTILEB)
#define GSMEM  (2 * GSTAGE)      // 81920

template<bool BF16OUT>
__device__ __forceinline__
void gemm_body(const __nv_bfloat16* __restrict__ Ah, const __nv_bfloat16* __restrict__ Al,
               const __nv_bfloat16* __restrict__ Bh, const __nv_bfloat16* __restrict__ Bl,
               float* __restrict__ C, __nv_bfloat16* __restrict__ Ch,
               __nv_bfloat16* __restrict__ Cl, int bm, int bn, char* sm)
{
    const uint32_t sb = smem_u32(sm);
    const int tid  = threadIdx.x;
    const int lane = tid & 31;
    const int wid  = tid >> 5;
    const int wm   = wid >> 2;
    const int wn   = wid & 3;

    const int lt = tid >> 6;
    const int u  = tid & 63;
    const int lrow0 = u >> 2;
    const int lcseg = (u & 3) * 16;
    const char* gsrc;
    {
        const char* s0 = (const char*)(Ah + (size_t)bm * EDIM);
        const char* s1 = (const char*)(Al + (size_t)bm * EDIM);
        const char* s2 = (const char*)(Bh + (size_t)bn * EDIM);
        const char* s3 = (const char*)(Bl + (size_t)bn * EDIM);
        gsrc = (lt == 0) ? s0 : (lt == 1) ? s1 : (lt == 2) ? s2 : s3;
    }
    const uint32_t sdst0 = sb + lt * GTILEB + lrow0 * GSTR + lcseg;

    auto issue = [&](int c, int st) {
        const char* g = gsrc + (size_t)lrow0 * 2048 + (size_t)c * 64 + lcseg;
        uint32_t s = sdst0 + st * GSTAGE;
#pragma unroll
        for (int i = 0; i < 8; ++i)
            CP_ASYNC16(s + i * 16 * GSTR, g + (size_t)i * 16 * 2048);
        CP_COMMIT();
    };

    const uint32_t offA = (uint32_t)((wm * 64 + (lane & 15)) * GSTR + (lane >> 4) * 16);
    const uint32_t offB = (uint32_t)((wn * 32 + (lane & 7) + (lane >> 4) * 8) * GSTR
                                     + ((lane >> 3) & 1) * 16);

    float acc[4][4][4];
#pragma unroll
    for (int i = 0; i < 4; ++i)
#pragma unroll
        for (int j = 0; j < 4; ++j)
#pragma unroll
            for (int k = 0; k < 4; ++k) acc[i][j][k] = 0.f;

    issue(0, 0);
    issue(1, 1);

    for (int c = 0; c < 32; ++c) {
        CP_WAIT1();
        __syncthreads();

        const uint32_t stb = sb + (c & 1) * GSTAGE;
        const uint32_t tAh = stb, tAl = stb + GTILEB;
        const uint32_t tBh = stb + 2 * GTILEB, tBl = stb + 3 * GTILEB;

#pragma unroll
        for (int ks = 0; ks < 2; ++ks) {
            const uint32_t ko = ks * 32;
            uint32_t ah[4][4], al[4][4], bh[2][4], bl[2][4];
#pragma unroll
            for (int mf = 0; mf < 4; ++mf) {
                ldm_x4(ah[mf], tAh + offA + mf * (16 * GSTR) + ko);
                ldm_x4(al[mf], tAl + offA + mf * (16 * GSTR) + ko);
            }
#pragma unroll
            for (int nf = 0; nf < 2; ++nf) {
                ldm_x4(bh[nf], tBh + offB + nf * (16 * GSTR) + ko);
                ldm_x4(bl[nf], tBl + offB + nf * (16 * GSTR) + ko);
            }
#pragma unroll
            for (int mf = 0; mf < 4; ++mf)
#pragma unroll
                for (int nf = 0; nf < 4; ++nf) {
                    const uint32_t* BH = &bh[nf >> 1][(nf & 1) * 2];
                    const uint32_t* BL = &bl[nf >> 1][(nf & 1) * 2];
                    hmma(acc[mf][nf], ah[mf], BH);
                    hmma(acc[mf][nf], ah[mf], BL);
                    hmma(acc[mf][nf], al[mf], BH);
                }
        }
        __syncthreads();
        if (c + 2 < 32) issue(c + 2, c & 1);
    }

    const int mrow = bm + wm * 64 + (lane >> 2);
    const int ncol = bn + wn * 32 + (lane & 3) * 2;
#pragma unroll
    for (int mf = 0; mf < 4; ++mf)
#pragma unroll
        for (int nf = 0; nf < 4; ++nf) {
            size_t i0 = (size_t)(mrow + mf * 16) * EDIM + ncol + nf * 8;
            size_t i1 = i0 + 8 * EDIM;
            if (BF16OUT) {
                store_split2(Ch, Cl, i0, acc[mf][nf][0], acc[mf][nf][1]);
                store_split2(Ch, Cl, i1, acc[mf][nf][2], acc[mf][nf][3]);
            } else {
                *(float2*)(C + i0) = make_float2(acc[mf][nf][0], acc[mf][nf][1]);
                *(float2*)(C + i1) = make_float2(acc[mf][nf][2], acc[mf][nf][3]);
            }
        }
}

// Q/K/V projections in ONE launch (grid.z selects weight & destination)
__global__ __launch_bounds__(256, 2)
void gemm_qkv(const __nv_bfloat16* __restrict__ xh, const __nv_bfloat16* __restrict__ xl,
              const __nv_bfloat16* __restrict__ wqh, const __nv_bfloat16* __restrict__ wql,
              const __nv_bfloat16* __restrict__ wkh, const __nv_bfloat16* __restrict__ wkl,
              const __nv_bfloat16* __restrict__ wvh, const __nv_bfloat16* __restrict__ wvl,
              __nv_bfloat16* __restrict__ qh, __nv_bfloat16* __restrict__ ql,
              __nv_bfloat16* __restrict__ kh, __nv_bfloat16* __restrict__ kl,
              __nv_bfloat16* __restrict__ vh, __nv_bfloat16* __restrict__ vl)
{
    extern __shared__ char sm[];
    const int z = blockIdx.z;
    const __nv_bfloat16* Bh = (z == 0) ? wqh : (z == 1) ? wkh : wvh;
    const __nv_bfloat16* Bl = (z == 0) ? wql : (z == 1) ? wkl : wvl;
    __nv_bfloat16* Ch = (z == 0) ? qh : (z == 1) ? kh : vh;
    __nv_bfloat16* Cl = (z == 0) ? ql : (z == 1) ? kl : vl;
    gemm_body<true>(xh, xl, Bh, Bl, nullptr, Ch, Cl,
                    blockIdx.y * 128, blockIdx.x * 128, sm);
}

__global__ __launch_bounds__(256, 2)
void gemm_out(const __nv_bfloat16* __restrict__ Ah, const __nv_bfloat16* __restrict__ Al,
              const __nv_bfloat16* __restrict__ Bh, const __nv_bfloat16* __restrict__ Bl,
              float* __restrict__ C)
{
    extern __shared__ char sm[];
    gemm_body<false>(Ah, Al, Bh, Bl, C, nullptr, nullptr,
                     blockIdx.y * 128, blockIdx.x * 128, sm);
}

// ---------------- lambda ----------------
__global__ void lambda_kernel(const float* __restrict__ lq1, const float* __restrict__ lk1,
                              const float* __restrict__ lq2, const float* __restrict__ lk2)
{
    const int lane = threadIdx.x;
    float a = lq1[lane] * lk1[lane];
    float b = lq2[lane] * lk2[lane];
#pragma unroll
    for (int off = 16; off; off >>= 1) {
        a += __shfl_xor_sync(0xffffffffu, a, off);
        b += __shfl_xor_sync(0xffffffffu, b, off);
    }
    if (lane == 0) g_lambda = __expf(a) - __expf(b) + LAMBDA_INIT_C;
}

// ============================================================================
// Tensor-core flash (R13/R15 config: 512 CTAs, one head per CTA).
// ============================================================================
#define QT 128
#define KT 64
#define VSTR 144
#define FQ(sp)        ((sp) * 10240)
#define FK(st, sp)    (20480 + (st) * 10240 + (sp) * 5120)
#define FV(st, sp)    (40960 + (st) * 18432 + (sp) * 9216)
#define FSMEM 77824

__global__ __launch_bounds__(256)
void diff_flash_tc(const __nv_bfloat16* __restrict__ Qh, const __nv_bfloat16* __restrict__ Ql,
                   const __nv_bfloat16* __restrict__ Kh, const __nv_bfloat16* __restrict__ Kl,
                   const __nv_bfloat16* __restrict__ Vh, const __nv_bfloat16* __restrict__ Vl,
                   float* __restrict__ O)
{
    extern __shared__ char sm[];
    const uint32_t sb = smem_u32(sm);
    const int tid  = threadIdx.x;
    const int lane = tid & 31;
    const int wq   = tid >> 5;
    const int h    = blockIdx.y;
    const int it   = gridDim.x - 1 - blockIdx.x;
    const int qbase = it * QT;
    const int qoff  = h * HD;
    const int voff  = (h >> 1) * DV;
    const int njt   = 2 * it + 2;

#pragma unroll
    for (int sp = 0; sp < 2; ++sp) {
        const __nv_bfloat16* src = sp ? Ql : Qh;
#pragma unroll
        for (int i = 0; i < 2; ++i) {
            int seg = tid + i * 256;
            int row = seg >> 2, c = (seg & 3) * 16;
            CP_ASYNC16(sb + FQ(sp) + row * GSTR + c,
                       (const char*)(src + (size_t)(qbase + row) * EDIM + qoff) + c);
        }
    }
    CP_COMMIT();

    auto load_kv = [&](int jt, int st) {
        {
            int row = tid >> 2, c = (tid & 3) * 16;
            CP_ASYNC16(sb + FK(st, 0) + row * GSTR + c,
                       (const char*)(Kh + (size_t)(jt * KT + row) * EDIM + qoff) + c);
            CP_ASYNC16(sb + FK(st, 1) + row * GSTR + c,
                       (const char*)(Kl + (size_t)(jt * KT + row) * EDIM + qoff) + c);
        }
#pragma unroll
        for (int i = 0; i < 2; ++i) {
            int seg = tid + i * 256;
            int row = seg >> 3, c = (seg & 7) * 16;
            CP_ASYNC16(sb + FV(st, 0) + row * VSTR + c,
                       (const char*)(Vh + (size_t)(jt * KT + row) * EDIM + voff) + c);
            CP_ASYNC16(sb + FV(st, 1) + row * VSTR + c,
                       (const char*)(Vl + (size_t)(jt * KT + row) * EDIM + voff) + c);
        }
        CP_COMMIT();
    };
    load_kv(0, 0);
    load_kv(1, 1);

    uint32_t qfh[2][4], qfl[2][4];
    CP_WAIT2();
    __syncthreads();
    {
        const uint32_t oa = (uint32_t)((wq * 16 + (lane & 15)) * GSTR + (lane >> 4) * 16);
#pragma unroll
        for (int ks = 0; ks < 2; ++ks) {
            ldm_x4(qfh[ks], sb + FQ(0) + oa + ks * 32);
            ldm_x4(qfl[ks], sb + FQ(1) + oa + ks * 32);
        }
    }

    float of[8][4];
#pragma unroll
    for (int nf = 0; nf < 8; ++nf)
#pragma unroll
        for (int e = 0; e < 4; ++e) of[nf][e] = 0.f;
    float l0 = 0.f, l1 = 0.f;

    const int row0 = qbase + wq * 16 + (lane >> 2);
    const int row1 = row0 + 8;
    const int rmax = qbase + wq * 16 + 15;

    for (int jt = 0; jt < njt; ++jt) {
        CP_WAIT1();
        __syncthreads();
        const int st = jt & 1;

        if ((jt * KT) <= rmax) {
            float sf[8][4];
#pragma unroll
            for (int nf = 0; nf < 8; ++nf)
#pragma unroll
                for (int e = 0; e < 4; ++e) sf[nf][e] = 0.f;
            const uint32_t kb = (uint32_t)((lane & 7) + (lane >> 4) * 8) * GSTR
                                + ((lane >> 3) & 1) * 16;
#pragma unroll
            for (int ks = 0; ks < 2; ++ks) {
#pragma unroll
                for (int nb = 0; nb < 4; ++nb) {
                    uint32_t bh4[4], bl4[4];
                    const uint32_t ob = kb + nb * (16 * GSTR) + ks * 32;
                    ldm_x4(bh4, sb + FK(st, 0) + ob);
                    ldm_x4(bl4, sb + FK(st, 1) + ob);
                    hmma(sf[2 * nb],     qfh[ks], bh4);
                    hmma(sf[2 * nb + 1], qfh[ks], bh4 + 2);
                    hmma(sf[2 * nb],     qfh[ks], bl4);
                    hmma(sf[2 * nb + 1], qfh[ks], bl4 + 2);
                    hmma(sf[2 * nb],     qfl[ks], bh4);
                    hmma(sf[2 * nb + 1], qfl[ks], bh4 + 2);
                }
            }

            const bool need_mask = (jt * KT + KT - 1) > (qbase + wq * 16);
            if (need_mask) {
#pragma unroll
                for (int nf = 0; nf < 8; ++nf) {
                    const int col = jt * KT + nf * 8 + (lane & 3) * 2;
                    sf[nf][0] = (col     <= row0) ? fexps(sf[nf][0]) : 0.f;
                    sf[nf][1] = (col + 1 <= row0) ? fexps(sf[nf][1]) : 0.f;
                    sf[nf][2] = (col     <= row1) ? fexps(sf[nf][2]) : 0.f;
                    sf[nf][3] = (col + 1 <= row1) ? fexps(sf[nf][3]) : 0.f;
                    l0 += sf[nf][0] + sf[nf][1];
                    l1 += sf[nf][2] + sf[nf][3];
                }
            } else {
#pragma unroll
                for (int nf = 0; nf < 8; ++nf) {
                    sf[nf][0] = fexps(sf[nf][0]);
                    sf[nf][1] = fexps(sf[nf][1]);
                    sf[nf][2] = fexps(sf[nf][2]);
                    sf[nf][3] = fexps(sf[nf][3]);
                    l0 += sf[nf][0] + sf[nf][1];
                    l1 += sf[nf][2] + sf[nf][3];
                }
            }

            uint32_t pha[4][4], pla[4][4];
#pragma unroll
            for (int kf = 0; kf < 4; ++kf) {
                pha[kf][0] = packsplit(sf[2 * kf][0],     sf[2 * kf][1],     pla[kf][0]);
                pha[kf][1] = packsplit(sf[2 * kf][2],     sf[2 * kf][3],     pla[kf][1]);
                pha[kf][2] = packsplit(sf[2 * kf + 1][0], sf[2 * kf + 1][1], pla[kf][2]);
                pha[kf][3] = packsplit(sf[2 * kf + 1][2], sf[2 * kf + 1][3], pla[kf][3]);
            }

            const uint32_t vb = (uint32_t)((lane & 7) + ((lane >> 3) & 1) * 8) * VSTR
                                + (lane >> 4) * 16;
#pragma unroll
            for (int kf = 0; kf < 4; ++kf) {
#pragma unroll
                for (int nb = 0; nb < 4; ++nb) {
                    uint32_t vh4[4], vl4[4];
                    const uint32_t ov = vb + kf * (16 * VSTR) + nb * 32;
                    ldm_x4_t(vh4, sb + FV(st, 0) + ov);
                    ldm_x4_t(vl4, sb + FV(st, 1) + ov);
                    hmma(of[2 * nb],     pha[kf], vh4);
                    hmma(of[2 * nb + 1], pha[kf], vh4 + 2);
                    hmma(of[2 * nb],     pha[kf], vl4);
                    hmma(of[2 * nb + 1], pha[kf], vl4 + 2);
                    hmma(of[2 * nb],     pla[kf], vh4);
                    hmma(of[2 * nb + 1], pla[kf], vh4 + 2);
                }
            }
        }

        __syncthreads();
        if (jt + 2 < njt) load_kv(jt + 2, st);
    }

    float t0 = l0, t1 = l1;
    t0 += __shfl_xor_sync(0xffffffffu, t0, 1);
    t0 += __shfl_xor_sync(0xffffffffu, t0, 2);
    t1 += __shfl_xor_sync(0xffffffffu, t1, 1);
    t1 += __shfl_xor_sync(0xffffffffu, t1, 2);
    const float inv0 = 1.f / t0, inv1 = 1.f / t1;
#pragma unroll
    for (int nf = 0; nf < 8; ++nf) {
        const int col = nf * 8 + (lane & 3) * 2;
        *(float2*)(O + ((size_t)h * TSEQ + row0) * DV + col) =
            make_float2(of[nf][0] * inv0, of[nf][1] * inv0);
        *(float2*)(O + ((size_t)h * TSEQ + row1) * DV + col) =
            make_float2(of[nf][2] * inv1, of[nf][3] * inv1);
    }
}

// ---------------- combine + bf16 split (fused) ----------------
__global__ __launch_bounds__(256)
void combine_split(const float* __restrict__ O, const float* __restrict__ gamma,
                   __nv_bfloat16* __restrict__ Ah, __nv_bfloat16* __restrict__ Al)
{
    const int tid = threadIdx.x, warp = tid >> 5, lane = tid & 31;
    const int g = blockIdx.x * 8 + warp;
    const int t = g >> 4, h = g & 15;
    const float lam = g_lambda, w = 1.0f - LAMBDA_INIT_C;

    const size_t b1 = ((size_t)(2 * h) * TSEQ + t) * DV;
    const size_t b2 = ((size_t)(2 * h + 1) * TSEQ + t) * DV;
    const float o0 = O[b1 + lane]      - lam * O[b2 + lane];
    const float o1 = O[b1 + lane + 32] - lam * O[b2 + lane + 32];

    float ss = o0 * o0 + o1 * o1;
#pragma unroll
    for (int off = 16; off; off >>= 1)
        ss += __shfl_xor_sync(0xffffffffu, ss, off);
    const float r = rsqrtf(ss * (1.f / 64.f) + 1e-5f) * w;

    const float a0 = gamma[lane]      * o0 * r;
    const float a1 = gamma[lane + 32] * o1 * r;
    const size_t i0 = (size_t)t * EDIM + h * DV + lane;
    __nv_bfloat16 h0 = __float2bfloat16(a0), h1 = __float2bfloat16(a1);
    Ah[i0]      = h0;
    Ah[i0 + 32] = h1;
    Al[i0]      = __float2bfloat16(a0 - __bfloat162float(h0));
    Al[i0 + 32] = __float2bfloat16(a1 - __bfloat162float(h1));
}

// ---------------- launch ----------------
extern "C" void kernel_launch(void* const* d_in, const int* in_sizes, int n_in,
                              void* d_out, int out_size)
{
    const float* x   = (const float*)d_in[0];
    const float* Wq  = (const float*)d_in[1];
    const float* Wk  = (const float*)d_in[2];
    const float* Wv  = (const float*)d_in[3];
    const float* Wo  = (const float*)d_in[4];
    const float* lq1 = (const float*)d_in[5];
    const float* lk1 = (const float*)d_in[6];
    const float* lq2 = (const float*)d_in[7];
    const float* lk2 = (const float*)d_in[8];
    const float* gam = (const float*)d_in[9];
    float* out = (float*)d_out;

    float *pO;
    __nv_bfloat16 *xh, *xl, *wqh, *wql, *wkh, *wkl, *wvh, *wvl, *woh, *wol, *ah, *al;
    __nv_bfloat16 *qh, *ql, *kh, *kl, *vh, *vl;
    cudaGetSymbolAddress((void**)&pO, g_Ohead);
    cudaGetSymbolAddress((void**)&xh, g_xh);   cudaGetSymbolAddress((void**)&xl, g_xl);
    cudaGetSymbolAddress((void**)&wqh, g_wqh); cudaGetSymbolAddress((void**)&wql, g_wql);
    cudaGetSymbolAddress((void**)&wkh, g_wkh); cudaGetSymbolAddress((void**)&wkl, g_wkl);
    cudaGetSymbolAddress((void**)&wvh, g_wvh); cudaGetSymbolAddress((void**)&wvl, g_wvl);
    cudaGetSymbolAddress((void**)&woh, g_woh); cudaGetSymbolAddress((void**)&wol, g_wol);
    cudaGetSymbolAddress((void**)&ah, g_ah);   cudaGetSymbolAddress((void**)&al, g_al);
    cudaGetSymbolAddress((void**)&qh, g_qh);   cudaGetSymbolAddress((void**)&ql, g_ql);
    cudaGetSymbolAddress((void**)&kh, g_kh);   cudaGetSymbolAddress((void**)&kl, g_kl);
    cudaGetSymbolAddress((void**)&vh, g_vh);   cudaGetSymbolAddress((void**)&vl, g_vl);

    cudaFuncSetAttribute(gemm_qkv, cudaFuncAttributeMaxDynamicSharedMemorySize, GSMEM);
    cudaFuncSetAttribute(gemm_out, cudaFuncAttributeMaxDynamicSharedMemorySize, GSMEM);
    cudaFuncSetAttribute(diff_flash_tc, cudaFuncAttributeMaxDynamicSharedMemorySize, FSMEM);

    const int nx = TSEQ * EDIM, nw = EDIM * EDIM;
    split_kernel<<<nx / 1024, 256>>>(x, xh, xl);
    dim3 gw(nw / 1024, 1, 4);
    split_w4<<<gw, 256>>>(Wq, Wk, Wv, Wo, wqh, wql, wkh, wkl, wvh, wvl, woh, wol);

    lambda_kernel<<<1, 32>>>(lq1, lk1, lq2, lk2);

    dim3 gq(EDIM / 128, TSEQ / 128, 3);
    gemm_qkv<<<gq, 256, GSMEM>>>(xh, xl, wqh, wql, wkh, wkl, wvh, wvl,
                                 qh, ql, kh, kl, vh, vl);

    dim3 fg(TSEQ / QT, NQH);
    diff_flash_tc<<<fg, 256, FSMEM>>>(qh, ql, kh, kl, vh, vl, pO);

    combine_split<<<(TSEQ * NH) / 8, 256>>>(pO, gam, ah, al);

    dim3 gg(EDIM / 128, TSEQ / 128);
    gemm_out<<<gg, 256, GSMEM>>>(ah, al, woh, wol, out);
}